// round 11
// baseline (speedup 1.0000x reference)
#include <cuda_runtime.h>
#include <cstdint>

#define CDIV(a,b) (((a)+(b)-1)/(b))

#define NN 100000
#define NE 1600000
#define SCAN_BS 512
#define NPART ((NN + SCAN_BS - 1) / SCAN_BS)   // 196

// ---------------- device scratch (static; no cudaMalloc) ----------------
__device__ int   g_deg[NN];
__device__ int   g_off[NN + 1];
__device__ int   g_pos[NE];
__device__ int   g_csr[NE];
__device__ int   g_part[256];
__device__ float g_h0 [(size_t)NN * 64];
__device__ float g_h1 [(size_t)NN * 64];
// split (hi,lo) bf16x2 pair tables: [row][k2] with k2 = channel/2
__device__ uint2 g_xs  [(size_t)NN * 32];
__device__ uint2 g_h0s [(size_t)NN * 32];
__device__ uint2 g_h1s [(size_t)NN * 32];
__device__ uint2 g_aggs[(size_t)NN * 32];
// pre-split weights: [layer][k2 of 128-K concat][col]; fin: [k2][col]
__device__ uint2 g_ws[3][64][64];
__device__ uint2 g_fws[32][32];

__device__ __forceinline__ const float* sel_buf(int s, const float* ext) {
    return s == 0 ? ext : (s == 1 ? g_h0 : g_h1);
}
__device__ __forceinline__ const uint2* sel_split(int s) {
    return s == 0 ? g_xs : (s == 1 ? g_h0s : g_h1s);
}

// ---------------- bf16 split helpers (R6 proven) ----------------
__device__ __forceinline__ void bsplit(float f, uint32_t& hu, float& lo) {
    hu = __float_as_uint(f) & 0xFFFF0000u;
    lo = f - __uint_as_float(hu);
}
__device__ __forceinline__ uint32_t cvt_bf16x2(float hi_elem, float lo_elem) {
    uint32_t r;
    asm("cvt.rn.bf16x2.f32 %0, %1, %2;" : "=r"(r) : "f"(hi_elem), "f"(lo_elem));
    return r;
}
__device__ __forceinline__ void split_pack2(float f0, float f1, uint32_t& hp, uint32_t& lp) {
    uint32_t h0, h1;
    float l0, l1;
    bsplit(f0, h0, l0);
    bsplit(f1, h1, l1);
    hp = (h0 >> 16) | h1;
    lp = cvt_bf16x2(l1, l0);
}
__device__ __forceinline__ void mma_bf16(float* c, const uint32_t* a, uint32_t b0, uint32_t b1) {
    asm volatile(
        "mma.sync.aligned.m16n8k16.row.col.f32.bf16.bf16.f32 "
        "{%0,%1,%2,%3}, {%4,%5,%6,%7}, {%8,%9}, {%0,%1,%2,%3};"
        : "+f"(c[0]), "+f"(c[1]), "+f"(c[2]), "+f"(c[3])
        : "r"(a[0]), "r"(a[1]), "r"(a[2]), "r"(a[3]), "r"(b0), "r"(b1));
}

// ---------------- CSR construction (R10 proven) ----------------
__global__ void k_zero_deg() {
    int i = blockIdx.x * blockDim.x + threadIdx.x;
    if (i < NN) g_deg[i] = 0;
}

__global__ void k_count_pos(const int* __restrict__ ei) {
    int e = blockIdx.x * blockDim.x + threadIdx.x;
    if (e < NE) g_pos[e] = atomicAdd(&g_deg[ei[NE + e]], 1);
}

__global__ void __launch_bounds__(SCAN_BS) k_blocksum() {
    __shared__ int ws[16];
    int i = blockIdx.x * SCAN_BS + threadIdx.x;
    int v = (i < NN) ? g_deg[i] : 0;
    #pragma unroll
    for (int o = 16; o > 0; o >>= 1) v += __shfl_down_sync(0xFFFFFFFFu, v, o);
    int lane = threadIdx.x & 31, wid = threadIdx.x >> 5;
    if (lane == 0) ws[wid] = v;
    __syncthreads();
    if (wid == 0) {
        int s = (lane < 16) ? ws[lane] : 0;
        #pragma unroll
        for (int o = 8; o > 0; o >>= 1) s += __shfl_down_sync(0xFFFFFFFFu, s, o);
        if (lane == 0) g_part[blockIdx.x] = s;
    }
}

__global__ void __launch_bounds__(SCAN_BS) k_offsets() {
    __shared__ int ws[16];
    __shared__ int sbase;
    int i = blockIdx.x * SCAN_BS + threadIdx.x;
    int lane = threadIdx.x & 31, wid = threadIdx.x >> 5;

    if (wid == 1) {
        int acc = 0;
        for (int j = lane; j < blockIdx.x; j += 32) acc += g_part[j];
        #pragma unroll
        for (int o = 16; o > 0; o >>= 1) acc += __shfl_down_sync(0xFFFFFFFFu, acc, o);
        if (lane == 0) sbase = acc;
    }

    int v = (i < NN) ? g_deg[i] : 0;
    int incl = v;
    #pragma unroll
    for (int o = 1; o < 32; o <<= 1) {
        int u = __shfl_up_sync(0xFFFFFFFFu, incl, o);
        if (lane >= o) incl += u;
    }
    if (lane == 31) ws[wid] = incl;
    __syncthreads();
    if (wid == 0) {
        int s = (lane < 16) ? ws[lane] : 0;
        int si = s;
        #pragma unroll
        for (int o = 1; o < 32; o <<= 1) {
            int u = __shfl_up_sync(0xFFFFFFFFu, si, o);
            if (lane >= o) si += u;
        }
        if (lane < 16) ws[lane] = si - s;
    }
    __syncthreads();
    if (i < NN) g_off[i] = sbase + ws[wid] + incl - v;
    if (blockIdx.x == 0 && threadIdx.x == 0) g_off[NN] = NE;
}

__global__ void k_scatter2(const int* __restrict__ ei) {
    int e = blockIdx.x * blockDim.x + threadIdx.x;
    if (e < NE) {
        int src = ei[e];
        int dst = ei[NE + e];
        g_csr[g_off[dst] + g_pos[e]] = src;
    }
}

// ---------------- pre-split weights & x ----------------
__global__ void k_wsplit(const float* __restrict__ Wl1, const float* __restrict__ Wr1,
                         const float* __restrict__ Wl2, const float* __restrict__ Wr2,
                         const float* __restrict__ Wl3, const float* __restrict__ Wr3,
                         const float* __restrict__ Wfin) {
    int j = blockIdx.x * blockDim.x + threadIdx.x;
    if (j < 3 * 64 * 64) {
        int layer = j >> 12;
        int r  = j & 4095;
        int k2 = r >> 6;
        int cc = r & 63;
        const float* Wl = layer == 0 ? Wl1 : (layer == 1 ? Wl2 : Wl3);
        const float* Wr = layer == 0 ? Wr1 : (layer == 1 ? Wr2 : Wr3);
        float w0, w1;
        if (k2 < 32) {
            w0 = Wl[(size_t)(2 * k2) * 64 + cc];
            w1 = Wl[(size_t)(2 * k2 + 1) * 64 + cc];
        } else {
            int kk = k2 - 32;
            w0 = Wr[(size_t)(2 * kk) * 64 + cc];
            w1 = Wr[(size_t)(2 * kk + 1) * 64 + cc];
        }
        uint32_t hp, lp;
        split_pack2(w0, w1, hp, lp);
        g_ws[layer][k2][cc] = make_uint2(hp, lp);
    } else if (j < 3 * 64 * 64 + 32 * 32) {
        int jj = j - 3 * 64 * 64;
        int k2 = jj >> 5;
        int cc = jj & 31;
        float w0 = Wfin[(size_t)(2 * k2) * 32 + cc];
        float w1 = Wfin[(size_t)(2 * k2 + 1) * 32 + cc];
        uint32_t hp, lp;
        split_pack2(w0, w1, hp, lp);
        g_fws[k2][cc] = make_uint2(hp, lp);
    }
}

__global__ void k_xsplit(const float* __restrict__ x) {
    int i = blockIdx.x * blockDim.x + threadIdx.x;
    if (i < NN * 32) {
        float2 v = ((const float2*)x)[i];
        uint32_t hp, lp;
        split_pack2(v.x, v.y, hp, lp);
        g_xs[i] = make_uint2(hp, lp);
    }
}

// ---------------- mean aggregation (writes SPLIT agg table) ----------------
__global__ void k_agg(const float* __restrict__ xext, int xsel) {
    int gw   = (blockIdx.x * blockDim.x + threadIdx.x) >> 5;
    int lane = threadIdx.x & 31;
    if (gw >= NN) return;
    const float* __restrict__ x = sel_buf(xsel, xext);
    const float4* __restrict__ x4 = (const float4*)x;
    int beg = g_off[gw];
    int end = g_off[gw + 1];
    int half = lane >> 4;
    int li   = lane & 15;
    float4 acc = make_float4(0.f, 0.f, 0.f, 0.f);
    int e = beg + half;
    #pragma unroll 1
    for (; e + 6 < end; e += 8) {
        int s0 = g_csr[e];
        int s1 = g_csr[e + 2];
        int s2 = g_csr[e + 4];
        int s3 = g_csr[e + 6];
        float4 v0 = x4[(size_t)s0 * 16 + li];
        float4 v1 = x4[(size_t)s1 * 16 + li];
        float4 v2 = x4[(size_t)s2 * 16 + li];
        float4 v3 = x4[(size_t)s3 * 16 + li];
        acc.x += (v0.x + v1.x) + (v2.x + v3.x);
        acc.y += (v0.y + v1.y) + (v2.y + v3.y);
        acc.z += (v0.z + v1.z) + (v2.z + v3.z);
        acc.w += (v0.w + v1.w) + (v2.w + v3.w);
    }
    #pragma unroll 1
    for (; e < end; e += 2) {
        int s = g_csr[e];
        float4 v = x4[(size_t)s * 16 + li];
        acc.x += v.x; acc.y += v.y; acc.z += v.z; acc.w += v.w;
    }
    acc.x += __shfl_xor_sync(0xFFFFFFFFu, acc.x, 16);
    acc.y += __shfl_xor_sync(0xFFFFFFFFu, acc.y, 16);
    acc.z += __shfl_xor_sync(0xFFFFFFFFu, acc.z, 16);
    acc.w += __shfl_xor_sync(0xFFFFFFFFu, acc.w, 16);
    if (half == 0) {
        int d = end - beg;
        float inv = d > 0 ? 1.f / (float)d : 0.f;
        uint32_t h0_, l0_, h1_, l1_;
        split_pack2(acc.x * inv, acc.y * inv, h0_, l0_);
        split_pack2(acc.z * inv, acc.w * inv, h1_, l1_);
        ((uint4*)g_aggs)[(size_t)gw * 16 + li] = make_uint4(h0_, l0_, h1_, l1_);
    }
}

// ---------------- GEMM: copy-only staging from pre-split tables ----------------
// out = relu([agg | A1] @ Wcat + bias). Block 256 thr, tile 128 x 64.
// A: kt<64 from g_aggs, else from split h table (asel). B: g_ws[lidx].
// Non-fused epilogue stores h fp32 (for next agg) + h split (for next GEMM).
// FUSE_FIN: re-split relu'd fragments in-register, second MMA stage vs g_fws.
template <bool FUSE_FIN>
__global__ void __launch_bounds__(256)
k_gemm(int asel, int lidx, int dsel,
       const float* __restrict__ bias, const float* __restrict__ bfin,
       float* __restrict__ oext) {
    constexpr int BM   = 128;
    constexpr int LDAP = 136;
    constexpr int LDBP = 72;
    constexpr int MAIN_SZ = 2 * 16 * LDAP + 2 * 16 * LDBP;
    constexpr int FIN_SZ  = 2 * 32 * LDAP + 2 * 32 * 40;
    constexpr int BUF_SZ  = FUSE_FIN ? (FIN_SZ > MAIN_SZ ? FIN_SZ : MAIN_SZ) : MAIN_SZ;
    __shared__ uint32_t buf[BUF_SZ];

    uint32_t (*Ahp)[LDAP] = (uint32_t(*)[LDAP])(buf);
    uint32_t (*Alp)[LDAP] = (uint32_t(*)[LDAP])(buf + 16 * LDAP);
    uint32_t (*Bhp)[LDBP] = (uint32_t(*)[LDBP])(buf + 2 * 16 * LDAP);
    uint32_t (*Blp)[LDBP] = (uint32_t(*)[LDBP])(buf + 2 * 16 * LDAP + 16 * LDBP);

    const uint2* __restrict__ A1s = sel_split(asel);
    float* __restrict__ out = FUSE_FIN ? oext : (dsel == 1 ? g_h0 : g_h1);
    uint2* __restrict__ hsplit = (dsel == 1) ? g_h0s : g_h1s;

    const int t     = threadIdx.x;
    const int lane  = t & 31;
    const int wid   = t >> 5;
    const int g     = lane >> 2;
    const int tg    = lane & 3;
    const int mbase = blockIdx.x * BM;
    const int ma    = wid * 16 + g;

    uint2 va[8];
    uint2 vb[4];

    auto load_tile = [&](int kt) {
        const uint2* __restrict__ Asrc = (kt < 64) ? (const uint2*)g_aggs : A1s;
        const int kb2 = ((kt < 64) ? kt : (kt - 64)) >> 1;
        #pragma unroll
        for (int i = 0; i < 8; i++) {
            int idx = t + i * 256;
            int row = idx >> 4;
            int k2  = idx & 15;
            int grow = mbase + row;
            va[i] = (grow < NN) ? Asrc[(size_t)grow * 32 + kb2 + k2] : make_uint2(0u, 0u);
        }
        const int kg2 = kt >> 1;
        #pragma unroll
        for (int i = 0; i < 4; i++) {
            int idx = t + i * 256;
            int k2 = idx >> 6;
            int cc = idx & 63;
            vb[i] = g_ws[lidx][kg2 + k2][cc];
        }
    };

    float c[8][4];
    #pragma unroll
    for (int nt = 0; nt < 8; nt++)
        #pragma unroll
        for (int i = 0; i < 4; i++) c[nt][i] = 0.f;

    load_tile(0);

    #pragma unroll 1
    for (int kt = 0; kt < 128; kt += 32) {
        #pragma unroll
        for (int i = 0; i < 8; i++) {
            int idx = t + i * 256;
            int row = idx >> 4;
            int k2  = idx & 15;
            Ahp[k2][row] = va[i].x;
            Alp[k2][row] = va[i].y;
        }
        #pragma unroll
        for (int i = 0; i < 4; i++) {
            int idx = t + i * 256;
            int k2 = idx >> 6;
            int cc = idx & 63;
            Bhp[k2][cc] = vb[i].x;
            Blp[k2][cc] = vb[i].y;
        }
        __syncthreads();

        if (kt + 32 < 128) load_tile(kt + 32);

        #pragma unroll
        for (int ks = 0; ks < 2; ks++) {
            const int kk = ks * 8 + tg;
            uint32_t ah[4], al[4];
            ah[0] = Ahp[kk][ma];      ah[1] = Ahp[kk][ma + 8];
            ah[2] = Ahp[kk + 4][ma];  ah[3] = Ahp[kk + 4][ma + 8];
            al[0] = Alp[kk][ma];      al[1] = Alp[kk][ma + 8];
            al[2] = Alp[kk + 4][ma];  al[3] = Alp[kk + 4][ma + 8];
            #pragma unroll
            for (int nt = 0; nt < 8; nt++) {
                const int col = nt * 8 + g;
                uint32_t bh0 = Bhp[kk][col];
                uint32_t bh1 = Bhp[kk + 4][col];
                uint32_t bl0 = Blp[kk][col];
                uint32_t bl1 = Blp[kk + 4][col];
                mma_bf16(c[nt], al, bh0, bh1);
                mma_bf16(c[nt], ah, bl0, bl1);
                mma_bf16(c[nt], ah, bh0, bh1);
            }
        }
        __syncthreads();
    }

    const int r0 = mbase + wid * 16 + g;
    const int r1 = r0 + 8;

    if constexpr (!FUSE_FIN) {
        #pragma unroll
        for (int nt = 0; nt < 8; nt++) {
            const int col = nt * 8 + 2 * tg;
            const int k2  = nt * 4 + tg;
            float bx = bias[col];
            float by = bias[col + 1];
            if (r0 < NN) {
                float vx = fmaxf(c[nt][0] + bx, 0.f);
                float vy = fmaxf(c[nt][1] + by, 0.f);
                *(float2*)&out[(size_t)r0 * 64 + col] = make_float2(vx, vy);
                uint32_t hp, lp;
                split_pack2(vx, vy, hp, lp);
                hsplit[(size_t)r0 * 32 + k2] = make_uint2(hp, lp);
            }
            if (r1 < NN) {
                float vx = fmaxf(c[nt][2] + bx, 0.f);
                float vy = fmaxf(c[nt][3] + by, 0.f);
                *(float2*)&out[(size_t)r1 * 64 + col] = make_float2(vx, vy);
                uint32_t hp, lp;
                split_pack2(vx, vy, hp, lp);
                hsplit[(size_t)r1 * 32 + k2] = make_uint2(hp, lp);
            }
        }
    } else {
        uint32_t (*Fh)[LDAP] = (uint32_t(*)[LDAP])(buf);
        uint32_t (*Fl)[LDAP] = (uint32_t(*)[LDAP])(buf + 32 * LDAP);
        uint32_t (*B2h)[40]  = (uint32_t(*)[40])(buf + 2 * 32 * LDAP);
        uint32_t (*B2l)[40]  = (uint32_t(*)[40])(buf + 2 * 32 * LDAP + 32 * 40);

        const int rl0 = wid * 16 + g;
        const int rl1 = rl0 + 8;
        #pragma unroll
        for (int nt = 0; nt < 8; nt++) {
            const int col = nt * 8 + 2 * tg;
            const int k2  = nt * 4 + tg;
            float bx = bias[col];
            float by = bias[col + 1];
            float v0x = fmaxf(c[nt][0] + bx, 0.f);
            float v0y = fmaxf(c[nt][1] + by, 0.f);
            float v1x = fmaxf(c[nt][2] + bx, 0.f);
            float v1y = fmaxf(c[nt][3] + by, 0.f);
            uint32_t hp, lp;
            split_pack2(v0x, v0y, hp, lp);
            Fh[k2][rl0] = hp;
            Fl[k2][rl0] = lp;
            split_pack2(v1x, v1y, hp, lp);
            Fh[k2][rl1] = hp;
            Fl[k2][rl1] = lp;
        }
        #pragma unroll
        for (int idx = t; idx < 32 * 32; idx += 256) {
            int k2 = idx >> 5;
            int cc = idx & 31;
            uint2 w = g_fws[k2][cc];
            B2h[k2][cc] = w.x;
            B2l[k2][cc] = w.y;
        }
        __syncthreads();

        float c2[4][4];
        #pragma unroll
        for (int nt = 0; nt < 4; nt++)
            #pragma unroll
            for (int i = 0; i < 4; i++) c2[nt][i] = 0.f;

        #pragma unroll
        for (int ks = 0; ks < 4; ks++) {
            const int kk = ks * 8 + tg;
            uint32_t ah[4], al[4];
            ah[0] = Fh[kk][ma];      ah[1] = Fh[kk][ma + 8];
            ah[2] = Fh[kk + 4][ma];  ah[3] = Fh[kk + 4][ma + 8];
            al[0] = Fl[kk][ma];      al[1] = Fl[kk][ma + 8];
            al[2] = Fl[kk + 4][ma];  al[3] = Fl[kk + 4][ma + 8];
            #pragma unroll
            for (int nt = 0; nt < 4; nt++) {
                const int col = nt * 8 + g;
                uint32_t bh0 = B2h[kk][col];
                uint32_t bh1 = B2h[kk + 4][col];
                uint32_t bl0 = B2l[kk][col];
                uint32_t bl1 = B2l[kk + 4][col];
                mma_bf16(c2[nt], al, bh0, bh1);
                mma_bf16(c2[nt], ah, bl0, bl1);
                mma_bf16(c2[nt], ah, bh0, bh1);
            }
        }

        #pragma unroll
        for (int nt = 0; nt < 4; nt++) {
            const int col = nt * 8 + 2 * tg;
            float bx = bfin[col];
            float by = bfin[col + 1];
            if (r0 < NN)
                *(float2*)&oext[(size_t)r0 * 32 + col] = make_float2(c2[nt][0] + bx, c2[nt][1] + by);
            if (r1 < NN)
                *(float2*)&oext[(size_t)r1 * 32 + col] = make_float2(c2[nt][2] + bx, c2[nt][3] + by);
        }
    }
}

// ---------------- host launcher (pure kernel launches; graph-capturable) ----------------
extern "C" void kernel_launch(void* const* d_in, const int* in_sizes, int n_in,
                              void* d_out, int out_size) {
    const float* x    = (const float*)d_in[0];
    const int*   ei   = (const int*)d_in[1];
    const float* Wl1  = (const float*)d_in[2];
    const float* Wr1  = (const float*)d_in[3];
    const float* b1   = (const float*)d_in[4];
    const float* Wl2  = (const float*)d_in[5];
    const float* Wr2  = (const float*)d_in[6];
    const float* b2   = (const float*)d_in[7];
    const float* Wl3  = (const float*)d_in[8];
    const float* Wr3  = (const float*)d_in[9];
    const float* b3   = (const float*)d_in[10];
    const float* Wlin = (const float*)d_in[11];
    const float* blin = (const float*)d_in[12];
    float*       out  = (float*)d_out;

    // CSR build + weight/x pre-split (independent streams of work)
    k_zero_deg<<<CDIV(NN, 256), 256>>>();
    k_wsplit<<<CDIV(3 * 64 * 64 + 32 * 32, 256), 256>>>(Wl1, Wr1, Wl2, Wr2, Wl3, Wr3, Wlin);
    k_xsplit<<<CDIV(NN * 32, 256), 256>>>(x);
    k_count_pos<<<CDIV(NE, 256), 256>>>(ei);
    k_blocksum<<<NPART, SCAN_BS>>>();
    k_offsets<<<NPART, SCAN_BS>>>();
    k_scatter2<<<CDIV(NE, 256), 256>>>(ei);

    const int AGG_BLOCKS  = CDIV(NN, 8);
    const int GEMM_BLOCKS = CDIV(NN, 128);

    // layer 1: x -> h0
    k_agg<<<AGG_BLOCKS, 256>>>(x, 0);
    k_gemm<false><<<GEMM_BLOCKS, 256>>>(0, 0, 1, b1, nullptr, nullptr);
    // layer 2: h0 -> h1
    k_agg<<<AGG_BLOCKS, 256>>>(nullptr, 1);
    k_gemm<false><<<GEMM_BLOCKS, 256>>>(1, 1, 2, b2, nullptr, nullptr);
    // layer 3 + final linear fused: h1 -> out
    k_agg<<<AGG_BLOCKS, 256>>>(nullptr, 2);
    k_gemm<true><<<GEMM_BLOCKS, 256>>>(2, 2, 0, b3, blin, out);
}

// round 12
// speedup vs baseline: 1.1109x; 1.1109x over previous
#include <cuda_runtime.h>
#include <cstdint>

#define CDIV(a,b) (((a)+(b)-1)/(b))

#define NN 100000
#define NE 1600000
#define SCAN_BS 512
#define NPART ((NN + SCAN_BS - 1) / SCAN_BS)   // 196

// ---------------- device scratch (static; no cudaMalloc) ----------------
__device__ int   g_deg[NN];
__device__ int   g_off[NN + 1];
__device__ int   g_pos[NE];
__device__ int   g_csr[NE];
__device__ int   g_part[256];
__device__ float g_agg[(size_t)NN * 64];
__device__ float g_h0 [(size_t)NN * 64];
__device__ float g_h1 [(size_t)NN * 64];
// pre-split weights: [layer][k2 of 128-K concat][col] (hi,lo bf16x2); fin: [k2][col]
__device__ uint2 g_ws[3][64][64];
__device__ uint2 g_fws[32][32];

__device__ __forceinline__ const float* sel_buf(int s, const float* ext) {
    return s == 0 ? ext : (s == 1 ? g_h0 : g_h1);
}

// ---------------- bf16 split helpers (R6 proven) ----------------
__device__ __forceinline__ void bsplit(float f, uint32_t& hu, float& lo) {
    hu = __float_as_uint(f) & 0xFFFF0000u;
    lo = f - __uint_as_float(hu);
}
__device__ __forceinline__ uint32_t cvt_bf16x2(float hi_elem, float lo_elem) {
    uint32_t r;
    asm("cvt.rn.bf16x2.f32 %0, %1, %2;" : "=r"(r) : "f"(hi_elem), "f"(lo_elem));
    return r;
}
__device__ __forceinline__ void split_pack2(float f0, float f1, uint32_t& hp, uint32_t& lp) {
    uint32_t h0, h1;
    float l0, l1;
    bsplit(f0, h0, l0);
    bsplit(f1, h1, l1);
    hp = (h0 >> 16) | h1;
    lp = cvt_bf16x2(l1, l0);
}
__device__ __forceinline__ void mma_bf16(float* c, const uint32_t* a, uint32_t b0, uint32_t b1) {
    asm volatile(
        "mma.sync.aligned.m16n8k16.row.col.f32.bf16.bf16.f32 "
        "{%0,%1,%2,%3}, {%4,%5,%6,%7}, {%8,%9}, {%0,%1,%2,%3};"
        : "+f"(c[0]), "+f"(c[1]), "+f"(c[2]), "+f"(c[3])
        : "r"(a[0]), "r"(a[1]), "r"(a[2]), "r"(a[3]), "r"(b0), "r"(b1));
}

// ---------------- CSR construction (R10 proven) ----------------
__global__ void k_zero_deg() {
    int i = blockIdx.x * blockDim.x + threadIdx.x;
    if (i < NN) g_deg[i] = 0;
}

__global__ void k_count_pos(const int* __restrict__ ei) {
    int e = blockIdx.x * blockDim.x + threadIdx.x;
    if (e < NE) g_pos[e] = atomicAdd(&g_deg[ei[NE + e]], 1);
}

__global__ void __launch_bounds__(SCAN_BS) k_blocksum() {
    __shared__ int ws[16];
    int i = blockIdx.x * SCAN_BS + threadIdx.x;
    int v = (i < NN) ? g_deg[i] : 0;
    #pragma unroll
    for (int o = 16; o > 0; o >>= 1) v += __shfl_down_sync(0xFFFFFFFFu, v, o);
    int lane = threadIdx.x & 31, wid = threadIdx.x >> 5;
    if (lane == 0) ws[wid] = v;
    __syncthreads();
    if (wid == 0) {
        int s = (lane < 16) ? ws[lane] : 0;
        #pragma unroll
        for (int o = 8; o > 0; o >>= 1) s += __shfl_down_sync(0xFFFFFFFFu, s, o);
        if (lane == 0) g_part[blockIdx.x] = s;
    }
}

__global__ void __launch_bounds__(SCAN_BS) k_offsets() {
    __shared__ int ws[16];
    __shared__ int sbase;
    int i = blockIdx.x * SCAN_BS + threadIdx.x;
    int lane = threadIdx.x & 31, wid = threadIdx.x >> 5;

    if (wid == 1) {
        int acc = 0;
        for (int j = lane; j < blockIdx.x; j += 32) acc += g_part[j];
        #pragma unroll
        for (int o = 16; o > 0; o >>= 1) acc += __shfl_down_sync(0xFFFFFFFFu, acc, o);
        if (lane == 0) sbase = acc;
    }

    int v = (i < NN) ? g_deg[i] : 0;
    int incl = v;
    #pragma unroll
    for (int o = 1; o < 32; o <<= 1) {
        int u = __shfl_up_sync(0xFFFFFFFFu, incl, o);
        if (lane >= o) incl += u;
    }
    if (lane == 31) ws[wid] = incl;
    __syncthreads();
    if (wid == 0) {
        int s = (lane < 16) ? ws[lane] : 0;
        int si = s;
        #pragma unroll
        for (int o = 1; o < 32; o <<= 1) {
            int u = __shfl_up_sync(0xFFFFFFFFu, si, o);
            if (lane >= o) si += u;
        }
        if (lane < 16) ws[lane] = si - s;
    }
    __syncthreads();
    if (i < NN) g_off[i] = sbase + ws[wid] + incl - v;
    if (blockIdx.x == 0 && threadIdx.x == 0) g_off[NN] = NE;
}

__global__ void k_scatter2(const int* __restrict__ ei) {
    int e = blockIdx.x * blockDim.x + threadIdx.x;
    if (e < NE) {
        int src = ei[e];
        int dst = ei[NE + e];
        g_csr[g_off[dst] + g_pos[e]] = src;
    }
}

// ---------------- pre-split weights ----------------
__global__ void k_wsplit(const float* __restrict__ Wl1, const float* __restrict__ Wr1,
                         const float* __restrict__ Wl2, const float* __restrict__ Wr2,
                         const float* __restrict__ Wl3, const float* __restrict__ Wr3,
                         const float* __restrict__ Wfin) {
    int j = blockIdx.x * blockDim.x + threadIdx.x;
    if (j < 3 * 64 * 64) {
        int layer = j >> 12;
        int r  = j & 4095;
        int k2 = r >> 6;
        int cc = r & 63;
        const float* Wl = layer == 0 ? Wl1 : (layer == 1 ? Wl2 : Wl3);
        const float* Wr = layer == 0 ? Wr1 : (layer == 1 ? Wr2 : Wr3);
        float w0, w1;
        if (k2 < 32) {
            w0 = Wl[(size_t)(2 * k2) * 64 + cc];
            w1 = Wl[(size_t)(2 * k2 + 1) * 64 + cc];
        } else {
            int kk = k2 - 32;
            w0 = Wr[(size_t)(2 * kk) * 64 + cc];
            w1 = Wr[(size_t)(2 * kk + 1) * 64 + cc];
        }
        uint32_t hp, lp;
        split_pack2(w0, w1, hp, lp);
        g_ws[layer][k2][cc] = make_uint2(hp, lp);
    } else if (j < 3 * 64 * 64 + 32 * 32) {
        int jj = j - 3 * 64 * 64;
        int k2 = jj >> 5;
        int cc = jj & 31;
        float w0 = Wfin[(size_t)(2 * k2) * 32 + cc];
        float w1 = Wfin[(size_t)(2 * k2 + 1) * 32 + cc];
        uint32_t hp, lp;
        split_pack2(w0, w1, hp, lp);
        g_fws[k2][cc] = make_uint2(hp, lp);
    }
}

// ---------------- mean aggregation (R10 proven) ----------------
__global__ void k_agg(const float* __restrict__ xext, int xsel) {
    int gw   = (blockIdx.x * blockDim.x + threadIdx.x) >> 5;
    int lane = threadIdx.x & 31;
    if (gw >= NN) return;
    const float* __restrict__ x = sel_buf(xsel, xext);
    const float4* __restrict__ x4 = (const float4*)x;
    int beg = g_off[gw];
    int end = g_off[gw + 1];
    int half = lane >> 4;
    int li   = lane & 15;
    float4 acc = make_float4(0.f, 0.f, 0.f, 0.f);
    int e = beg + half;
    #pragma unroll 1
    for (; e + 6 < end; e += 8) {
        int s0 = g_csr[e];
        int s1 = g_csr[e + 2];
        int s2 = g_csr[e + 4];
        int s3 = g_csr[e + 6];
        float4 v0 = x4[(size_t)s0 * 16 + li];
        float4 v1 = x4[(size_t)s1 * 16 + li];
        float4 v2 = x4[(size_t)s2 * 16 + li];
        float4 v3 = x4[(size_t)s3 * 16 + li];
        acc.x += (v0.x + v1.x) + (v2.x + v3.x);
        acc.y += (v0.y + v1.y) + (v2.y + v3.y);
        acc.z += (v0.z + v1.z) + (v2.z + v3.z);
        acc.w += (v0.w + v1.w) + (v2.w + v3.w);
    }
    #pragma unroll 1
    for (; e < end; e += 2) {
        int s = g_csr[e];
        float4 v = x4[(size_t)s * 16 + li];
        acc.x += v.x; acc.y += v.y; acc.z += v.z; acc.w += v.w;
    }
    acc.x += __shfl_xor_sync(0xFFFFFFFFu, acc.x, 16);
    acc.y += __shfl_xor_sync(0xFFFFFFFFu, acc.y, 16);
    acc.z += __shfl_xor_sync(0xFFFFFFFFu, acc.z, 16);
    acc.w += __shfl_xor_sync(0xFFFFFFFFu, acc.w, 16);
    if (half == 0) {
        int d = end - beg;
        float inv = d > 0 ? 1.f / (float)d : 0.f;
        acc.x *= inv; acc.y *= inv; acc.z *= inv; acc.w *= inv;
        ((float4*)g_agg)[(size_t)gw * 16 + li] = acc;
    }
}

// ---------------- double-buffered bf16 3-term split GEMM ----------------
// out = relu([agg | A1] @ Wcat + bias). Block 256 thr, tile 128 x 64, BK=16, 8 stages.
// Stage layout per buffer (uint32 words): Ah[8][136] @+0, Al @+1088, Bh[8][72] @+2176,
// Bl @+2752; stage stride 3328. While MMA consumes stage s, stage s+1 is split+stored.
// FUSE_FIN: re-split relu'd fragments into smem, second MMA vs g_fws, direct output.
template <bool FUSE_FIN>
__global__ void __launch_bounds__(256)
k_gemm(const float* __restrict__ xext, int asel, int lidx, int dsel,
       const float* __restrict__ bias, const float* __restrict__ bfin,
       float* __restrict__ oext) {
    constexpr int BM      = 128;
    constexpr int LDAP    = 136;
    constexpr int STAGE   = 3328;
    constexpr int MAIN_SZ = 2 * STAGE;                    // 6656
    constexpr int FIN_SZ  = 2 * 32 * LDAP + 2 * 32 * 40;  // 11264
    constexpr int BUF_SZ  = FUSE_FIN ? FIN_SZ : MAIN_SZ;
    __shared__ uint32_t buf[BUF_SZ];

    const float* __restrict__ A1 = sel_buf(asel, xext);
    const float* __restrict__ A0 = (const float*)g_agg;
    float* __restrict__ out = FUSE_FIN ? oext : (dsel == 1 ? g_h0 : g_h1);

    const int t     = threadIdx.x;
    const int lane  = t & 31;
    const int wid   = t >> 5;
    const int g     = lane >> 2;
    const int tg    = lane & 3;
    const int mbase = blockIdx.x * BM;
    const int ma    = wid * 16 + g;

    float2 va[4];
    uint2  vb[2];

    auto load_tile = [&](int s) {
        const bool second = (s >= 4);
        const float* __restrict__ Asrc = second ? A1 : A0;
        const int kb = (second ? (s - 4) : s) * 16;
        #pragma unroll
        for (int i = 0; i < 4; i++) {
            int idx = t + i * 256;
            int row = idx >> 3;
            int k2  = idx & 7;
            int grow = mbase + row;
            va[i] = (grow < NN) ? *(const float2*)&Asrc[(size_t)grow * 64 + kb + 2 * k2]
                                : make_float2(0.f, 0.f);
        }
        #pragma unroll
        for (int i = 0; i < 2; i++) {
            int idx = t + i * 256;
            int k2 = idx >> 6;
            int cc = idx & 63;
            vb[i] = g_ws[lidx][s * 8 + k2][cc];
        }
    };

    auto store_tile = [&](int bb) {
        #pragma unroll
        for (int i = 0; i < 4; i++) {
            int idx = t + i * 256;
            int row = idx >> 3;
            int k2  = idx & 7;
            uint32_t hp, lp;
            split_pack2(va[i].x, va[i].y, hp, lp);
            buf[bb + k2 * LDAP + row]        = hp;
            buf[bb + 1088 + k2 * LDAP + row] = lp;
        }
        #pragma unroll
        for (int i = 0; i < 2; i++) {
            int idx = t + i * 256;
            int k2 = idx >> 6;
            int cc = idx & 63;
            buf[bb + 2176 + k2 * 72 + cc] = vb[i].x;
            buf[bb + 2752 + k2 * 72 + cc] = vb[i].y;
        }
    };

    float c[8][4];
    #pragma unroll
    for (int nt = 0; nt < 8; nt++)
        #pragma unroll
        for (int i = 0; i < 4; i++) c[nt][i] = 0.f;

    load_tile(0);
    store_tile(0);
    __syncthreads();

    #pragma unroll 1
    for (int s = 0; s < 8; s++) {
        const int bb = (s & 1) * STAGE;
        if (s < 7) load_tile(s + 1);   // global loads in flight during mma

        const uint32_t* Ah = buf + bb;
        const uint32_t* Al = buf + bb + 1088;
        const uint32_t* Bh = buf + bb + 2176;
        const uint32_t* Bl = buf + bb + 2752;
        const int kk = tg;
        uint32_t ah[4], al[4];
        ah[0] = Ah[kk * LDAP + ma];        ah[1] = Ah[kk * LDAP + ma + 8];
        ah[2] = Ah[(kk + 4) * LDAP + ma];  ah[3] = Ah[(kk + 4) * LDAP + ma + 8];
        al[0] = Al[kk * LDAP + ma];        al[1] = Al[kk * LDAP + ma + 8];
        al[2] = Al[(kk + 4) * LDAP + ma];  al[3] = Al[(kk + 4) * LDAP + ma + 8];
        #pragma unroll
        for (int nt = 0; nt < 8; nt++) {
            const int col = nt * 8 + g;
            uint32_t bh0 = Bh[kk * 72 + col];
            uint32_t bh1 = Bh[(kk + 4) * 72 + col];
            uint32_t bl0 = Bl[kk * 72 + col];
            uint32_t bl1 = Bl[(kk + 4) * 72 + col];
            mma_bf16(c[nt], al, bh0, bh1);
            mma_bf16(c[nt], ah, bl0, bl1);
            mma_bf16(c[nt], ah, bh0, bh1);
        }

        if (s < 7) {
            store_tile((bb ^ STAGE));
            __syncthreads();
        }
    }
    __syncthreads();

    const int r0 = mbase + wid * 16 + g;
    const int r1 = r0 + 8;

    if constexpr (!FUSE_FIN) {
        #pragma unroll
        for (int nt = 0; nt < 8; nt++) {
            const int col = nt * 8 + 2 * tg;
            float bx = bias[col];
            float by = bias[col + 1];
            if (r0 < NN) {
                float vx = fmaxf(c[nt][0] + bx, 0.f);
                float vy = fmaxf(c[nt][1] + by, 0.f);
                *(float2*)&out[(size_t)r0 * 64 + col] = make_float2(vx, vy);
            }
            if (r1 < NN) {
                float vx = fmaxf(c[nt][2] + bx, 0.f);
                float vy = fmaxf(c[nt][3] + by, 0.f);
                *(float2*)&out[(size_t)r1 * 64 + col] = make_float2(vx, vy);
            }
        }
    } else {
        uint32_t (*Fh)[LDAP] = (uint32_t(*)[LDAP])(buf);
        uint32_t (*Fl)[LDAP] = (uint32_t(*)[LDAP])(buf + 32 * LDAP);
        uint32_t (*B2h)[40]  = (uint32_t(*)[40])(buf + 2 * 32 * LDAP);
        uint32_t (*B2l)[40]  = (uint32_t(*)[40])(buf + 2 * 32 * LDAP + 32 * 40);

        const int rl0 = wid * 16 + g;
        const int rl1 = rl0 + 8;
        #pragma unroll
        for (int nt = 0; nt < 8; nt++) {
            const int col = nt * 8 + 2 * tg;
            const int k2  = nt * 4 + tg;
            float bx = bias[col];
            float by = bias[col + 1];
            float v0x = fmaxf(c[nt][0] + bx, 0.f);
            float v0y = fmaxf(c[nt][1] + by, 0.f);
            float v1x = fmaxf(c[nt][2] + bx, 0.f);
            float v1y = fmaxf(c[nt][3] + by, 0.f);
            uint32_t hp, lp;
            split_pack2(v0x, v0y, hp, lp);
            Fh[k2][rl0] = hp;
            Fl[k2][rl0] = lp;
            split_pack2(v1x, v1y, hp, lp);
            Fh[k2][rl1] = hp;
            Fl[k2][rl1] = lp;
        }
        #pragma unroll
        for (int idx = t; idx < 32 * 32; idx += 256) {
            int k2 = idx >> 5;
            int cc = idx & 31;
            uint2 w = g_fws[k2][cc];
            B2h[k2][cc] = w.x;
            B2l[k2][cc] = w.y;
        }
        __syncthreads();

        float c2[4][4];
        #pragma unroll
        for (int nt = 0; nt < 4; nt++)
            #pragma unroll
            for (int i = 0; i < 4; i++) c2[nt][i] = 0.f;

        #pragma unroll
        for (int ks = 0; ks < 4; ks++) {
            const int kk = ks * 8 + tg;
            uint32_t ah[4], al[4];
            ah[0] = Fh[kk][ma];      ah[1] = Fh[kk][ma + 8];
            ah[2] = Fh[kk + 4][ma];  ah[3] = Fh[kk + 4][ma + 8];
            al[0] = Fl[kk][ma];      al[1] = Fl[kk][ma + 8];
            al[2] = Fl[kk + 4][ma];  al[3] = Fl[kk + 4][ma + 8];
            #pragma unroll
            for (int nt = 0; nt < 4; nt++) {
                const int col = nt * 8 + g;
                uint32_t bh0 = B2h[kk][col];
                uint32_t bh1 = B2h[kk + 4][col];
                uint32_t bl0 = B2l[kk][col];
                uint32_t bl1 = B2l[kk + 4][col];
                mma_bf16(c2[nt], al, bh0, bh1);
                mma_bf16(c2[nt], ah, bl0, bl1);
                mma_bf16(c2[nt], ah, bh0, bh1);
            }
        }

        #pragma unroll
        for (int nt = 0; nt < 4; nt++) {
            const int col = nt * 8 + 2 * tg;
            float bx = bfin[col];
            float by = bfin[col + 1];
            if (r0 < NN)
                *(float2*)&oext[(size_t)r0 * 32 + col] = make_float2(c2[nt][0] + bx, c2[nt][1] + by);
            if (r1 < NN)
                *(float2*)&oext[(size_t)r1 * 32 + col] = make_float2(c2[nt][2] + bx, c2[nt][3] + by);
        }
    }
}

// ---------------- host launcher (pure kernel launches; graph-capturable) ----------------
extern "C" void kernel_launch(void* const* d_in, const int* in_sizes, int n_in,
                              void* d_out, int out_size) {
    const float* x    = (const float*)d_in[0];
    const int*   ei   = (const int*)d_in[1];
    const float* Wl1  = (const float*)d_in[2];
    const float* Wr1  = (const float*)d_in[3];
    const float* b1   = (const float*)d_in[4];
    const float* Wl2  = (const float*)d_in[5];
    const float* Wr2  = (const float*)d_in[6];
    const float* b2   = (const float*)d_in[7];
    const float* Wl3  = (const float*)d_in[8];
    const float* Wr3  = (const float*)d_in[9];
    const float* b3   = (const float*)d_in[10];
    const float* Wlin = (const float*)d_in[11];
    const float* blin = (const float*)d_in[12];
    float*       out  = (float*)d_out;

    // CSR build + weight pre-split
    k_zero_deg<<<CDIV(NN, 256), 256>>>();
    k_wsplit<<<CDIV(3 * 64 * 64 + 32 * 32, 256), 256>>>(Wl1, Wr1, Wl2, Wr2, Wl3, Wr3, Wlin);
    k_count_pos<<<CDIV(NE, 256), 256>>>(ei);
    k_blocksum<<<NPART, SCAN_BS>>>();
    k_offsets<<<NPART, SCAN_BS>>>();
    k_scatter2<<<CDIV(NE, 256), 256>>>(ei);

    const int AGG_BLOCKS  = CDIV(NN, 8);
    const int GEMM_BLOCKS = CDIV(NN, 128);

    // layer 1: x -> h0
    k_agg<<<AGG_BLOCKS, 256>>>(x, 0);
    k_gemm<false><<<GEMM_BLOCKS, 256>>>(x, 0, 0, 1, b1, nullptr, nullptr);
    // layer 2: h0 -> h1
    k_agg<<<AGG_BLOCKS, 256>>>(nullptr, 1);
    k_gemm<false><<<GEMM_BLOCKS, 256>>>(nullptr, 1, 1, 2, b2, nullptr, nullptr);
    // layer 3 + final linear fused: h1 -> out
    k_agg<<<AGG_BLOCKS, 256>>>(nullptr, 2);
    k_gemm<true><<<GEMM_BLOCKS, 256>>>(nullptr, 2, 2, 0, b3, blin, out);
}